// round 17
// baseline (speedup 1.0000x reference)
#include <cuda_runtime.h>
#include <cstdint>
#include <math.h>

#define B_  2
#define L_  2048
#define D_  1024
#define H_  16
#define HD_ 64
#define SCALE_ 0.125f

#define NQKV ((size_t)B_ * H_ * L_ * HD_)
#define NX   ((size_t)B_ * L_ * D_)
#define NWQ  ((size_t)D_ * 3 * D_)
#define NWO  ((size_t)D_ * D_)
#define PKW  (D_ / 2)
#define XW   (D_ / 4)

// int8 limb planes + scales for QKV
__device__ uint32_t g_xq1[NX / 4], g_xq0[NX / 4];
__device__ uint32_t g_wq1[NWQ / 4], g_wq0[NWQ / 4];
__device__ float    g_sxa[B_ * L_];
__device__ float    g_swq[3 * D_];
// bf16x2 hi/lo planes (attention + out-proj)
__device__ uint32_t g_woh[NWO / 2], g_wol[NWO / 2];
__device__ uint32_t g_qh[NQKV / 2], g_ql[NQKV / 2];
__device__ uint32_t g_kh[NQKV / 2], g_kl[NQKV / 2];
__device__ uint32_t g_vth[NQKV / 2], g_vtl[NQKV / 2];
__device__ uint32_t g_ah[NX / 2],   g_al[NX / 2];

// ===========================================================================
// Helpers
// ===========================================================================
__device__ __forceinline__ void cp_async16(uint32_t dst, const void* src) {
    asm volatile("cp.async.cg.shared.global [%0], [%1], 16;"
                 :: "r"(dst), "l"(src) : "memory");
}
__device__ __forceinline__ void cp_commit() {
    asm volatile("cp.async.commit_group;" ::: "memory");
}
template<int N>
__device__ __forceinline__ void cp_wait() {
    asm volatile("cp.async.wait_group %0;" :: "n"(N) : "memory");
}
__device__ __forceinline__ uint32_t smem_u32(const void* p) {
    uint32_t a;
    asm("{ .reg .u64 t; cvta.to.shared.u64 t, %1; cvt.u32.u64 %0, t; }"
        : "=r"(a) : "l"(p));
    return a;
}
__device__ __forceinline__ uint32_t pack_bf16(float e0, float e1) {
    uint32_t d;
    asm("cvt.rn.bf16x2.f32 %0, %1, %2;" : "=r"(d) : "f"(e1), "f"(e0));
    return d;
}
__device__ __forceinline__ void bf16x2_split(float x0, float x1,
                                             uint32_t& hw, uint32_t& lw) {
    hw = pack_bf16(x0, x1);
    const float h0 = __uint_as_float(hw << 16);
    const float h1 = __uint_as_float(hw & 0xffff0000u);
    lw = pack_bf16(x0 - h0, x1 - h1);
}
__device__ __forceinline__ void quant_limbs(float x, float inv, int& a1, int& a0) {
    const float af = x * inv;
    const float a1f = rintf(af * 0.015625f);
    a1 = (int)a1f;
    a0 = (int)rintf(af - 64.f * a1f);
}
__device__ __forceinline__ uint32_t pack_s8x4(int a, int b, int c, int d) {
    return (uint32_t)(a & 0xff) | ((uint32_t)(b & 0xff) << 8) |
           ((uint32_t)(c & 0xff) << 16) | ((uint32_t)(d & 0xff) << 24);
}
#define MMA_BF16(c, a, b)                                                      \
    asm("mma.sync.aligned.m16n8k16.row.col.f32.bf16.bf16.f32 "                 \
        "{%0,%1,%2,%3}, {%4,%5,%6,%7}, {%8,%9}, {%0,%1,%2,%3};"                \
        : "+f"((c)[0]), "+f"((c)[1]), "+f"((c)[2]), "+f"((c)[3])               \
        : "r"((a)[0]), "r"((a)[1]), "r"((a)[2]), "r"((a)[3]),                  \
          "r"((b)[0]), "r"((b)[1]))
#define MMA_S8(c, a, b)                                                        \
    asm("mma.sync.aligned.m16n8k32.row.col.s32.s8.s8.s32 "                     \
        "{%0,%1,%2,%3}, {%4,%5,%6,%7}, {%8,%9}, {%0,%1,%2,%3};"                \
        : "+r"((c)[0]), "+r"((c)[1]), "+r"((c)[2]), "+r"((c)[3])               \
        : "r"((a)[0]), "r"((a)[1]), "r"((a)[2]), "r"((a)[3]),                  \
          "r"((b)[0]), "r"((b)[1]))
#define LDSM_X4(r0, r1, r2, r3, addr)                                          \
    asm volatile("ldmatrix.sync.aligned.m8n8.x4.shared.b16 {%0,%1,%2,%3}, [%4];" \
        : "=r"(r0), "=r"(r1), "=r"(r2), "=r"(r3) : "r"(addr))

// ===========================================================================
// Prep: 2 launches (R16, validated)
// ===========================================================================
#define CMB 12
#define WOB ((D_ / 64) * (D_ / 64))      // 256
#define XQB (B_ * L_)                    // 4096
#define WQB ((3 * D_ / 64) * (D_ / 64))  // 768

__global__ __launch_bounds__(256)
void prep1(const float* __restrict__ w_qkv, const float* __restrict__ w_out,
           float* __restrict__ swq,
           uint32_t* __restrict__ woh, uint32_t* __restrict__ wol)
{
    __shared__ float tsm[64][65];
    const int bid = blockIdx.x;
    const int tid = threadIdx.x;
    if (bid < CMB) {
        const int j = bid * 256 + tid;
        float mx = 0.f;
        for (int k = 0; k < D_; k += 4) {
            mx = fmaxf(mx, fabsf(w_qkv[(size_t)k * (3 * D_) + j]));
            mx = fmaxf(mx, fabsf(w_qkv[(size_t)(k + 1) * (3 * D_) + j]));
            mx = fmaxf(mx, fabsf(w_qkv[(size_t)(k + 2) * (3 * D_) + j]));
            mx = fmaxf(mx, fabsf(w_qkv[(size_t)(k + 3) * (3 * D_) + j]));
        }
        swq[j] = (mx > 0.f) ? mx * (1.f / 8128.f) : 1.f;
    } else {
        const int b = bid - CMB;
        const int n0 = (b % (D_ / 64)) * 64;
        const int k0 = (b / (D_ / 64)) * 64;
#pragma unroll
        for (int i = 0; i < 4; i++) {
            const int idx = tid + i * 256;
            const int kk = idx >> 4, n4 = (idx & 15) * 4;
            const float4 v = *reinterpret_cast<const float4*>(
                w_out + (size_t)(k0 + kk) * D_ + n0 + n4);
            tsm[kk][n4] = v.x; tsm[kk][n4 + 1] = v.y;
            tsm[kk][n4 + 2] = v.z; tsm[kk][n4 + 3] = v.w;
        }
        __syncthreads();
#pragma unroll
        for (int i = 0; i < 8; i++) {
            const int idx = tid + i * 256;
            const int nn = idx >> 5, k2 = idx & 31;
            uint32_t hw, lw;
            bf16x2_split(tsm[2 * k2][nn], tsm[2 * k2 + 1][nn], hw, lw);
            woh[(size_t)(n0 + nn) * PKW + k0 / 2 + k2] = hw;
            wol[(size_t)(n0 + nn) * PKW + k0 / 2 + k2] = lw;
        }
    }
}

__global__ __launch_bounds__(256)
void prep2(const float* __restrict__ x, const float* __restrict__ w_qkv,
           const float* __restrict__ swq,
           uint32_t* __restrict__ xq1, uint32_t* __restrict__ xq0,
           float* __restrict__ sxa,
           uint32_t* __restrict__ wq1, uint32_t* __restrict__ wq0)
{
    __shared__ float tsm[64][65];
    const int bid = blockIdx.x;
    const int tid = threadIdx.x;
    if (bid < XQB) {
        const int row = bid;
        const float4 v = reinterpret_cast<const float4*>(x + (size_t)row * D_)[tid];
        float mx = fmaxf(fmaxf(fabsf(v.x), fabsf(v.y)),
                         fmaxf(fabsf(v.z), fabsf(v.w)));
#pragma unroll
        for (int off = 16; off > 0; off >>= 1)
            mx = fmaxf(mx, __shfl_xor_sync(0xffffffffu, mx, off));
        if ((tid & 31) == 0) tsm[0][tid >> 5] = mx;
        __syncthreads();
        float m8 = tsm[0][0];
#pragma unroll
        for (int i = 1; i < 8; i++) m8 = fmaxf(m8, tsm[0][i]);
        const float s = (m8 > 0.f) ? m8 * (1.f / 8128.f) : 1.f;
        const float inv = (m8 > 0.f) ? 8128.f / m8 : 0.f;
        int a1[4], a0[4];
        quant_limbs(v.x, inv, a1[0], a0[0]);
        quant_limbs(v.y, inv, a1[1], a0[1]);
        quant_limbs(v.z, inv, a1[2], a0[2]);
        quant_limbs(v.w, inv, a1[3], a0[3]);
        xq1[(size_t)row * XW + tid] = pack_s8x4(a1[0], a1[1], a1[2], a1[3]);
        xq0[(size_t)row * XW + tid] = pack_s8x4(a0[0], a0[1], a0[2], a0[3]);
        if (tid == 0) sxa[row] = s;
    } else {
        const int b = bid - XQB;
        const int n0 = (b % (3 * D_ / 64)) * 64;
        const int k0 = (b / (3 * D_ / 64)) * 64;
#pragma unroll
        for (int i = 0; i < 4; i++) {
            const int idx = tid + i * 256;
            const int kk = idx >> 4, n4 = (idx & 15) * 4;
            const float4 v = *reinterpret_cast<const float4*>(
                w_qkv + (size_t)(k0 + kk) * (3 * D_) + n0 + n4);
            tsm[kk][n4] = v.x; tsm[kk][n4 + 1] = v.y;
            tsm[kk][n4 + 2] = v.z; tsm[kk][n4 + 3] = v.w;
        }
        __syncthreads();
#pragma unroll
        for (int i = 0; i < 4; i++) {
            const int idx = tid + i * 256;
            const int nn = idx >> 4, k4 = idx & 15;
            const float inv = 1.f / swq[n0 + nn];
            int a1[4], a0[4];
#pragma unroll
            for (int e = 0; e < 4; e++)
                quant_limbs(tsm[k4 * 4 + e][nn], inv, a1[e], a0[e]);
            const size_t off = (size_t)(n0 + nn) * XW + k0 / 4 + k4;
            wq1[off] = pack_s8x4(a1[0], a1[1], a1[2], a1[3]);
            wq0[off] = pack_s8x4(a0[0], a0[1], a0[2], a0[3]);
        }
    }
}

// ===========================================================================
// int8 limb IMMA QKV GEMM (R14, validated)
// ===========================================================================
#define IST 20
#define I_TF (128 * IST)
#define I_BUFW (4 * I_TF)
#define IGEMM_SMEM (2 * I_BUFW * 4)

__global__ __launch_bounds__(256, 1)
void gemm_i8_qkv(const uint32_t* __restrict__ Xq1, const uint32_t* __restrict__ Xq0,
                 const uint32_t* __restrict__ Wq1, const uint32_t* __restrict__ Wq0,
                 const float* __restrict__ sxa, const float* __restrict__ swq,
                 const float* __restrict__ bias,
                 uint32_t* __restrict__ qh, uint32_t* __restrict__ ql,
                 uint32_t* __restrict__ kh, uint32_t* __restrict__ kl,
                 uint32_t* __restrict__ vth, uint32_t* __restrict__ vtl,
                 float* __restrict__ kraw, float* __restrict__ vraw)
{
    extern __shared__ uint32_t smu[];
    const uint32_t sb = smem_u32(smu);

    const int tid  = threadIdx.x;
    const int wid  = tid >> 5;
    const int lane = tid & 31;
    const int g = lane >> 2;
    const int t = lane & 3;
    const int wm0 = (wid >> 2) * 64;
    const int wn0 = (wid & 3) * 32;
    const int m0 = blockIdx.y * 128;
    const int n0 = blockIdx.x * 128;

    int acc_hi[4][4][4], acc_mid[4][4][4];
#pragma unroll
    for (int mt = 0; mt < 4; mt++)
#pragma unroll
        for (int nt = 0; nt < 4; nt++)
#pragma unroll
            for (int r = 0; r < 4; r++) { acc_hi[mt][nt][r] = 0; acc_mid[mt][nt][r] = 0; }

    auto load_stage = [&](int s, int b) {
        const int kw0 = s * 16;
        const uint32_t a1 = sb + (uint32_t)(b * I_BUFW) * 4;
        const uint32_t a0 = a1 + I_TF * 4;
        const uint32_t b1 = a0 + I_TF * 4;
        const uint32_t b0 = b1 + I_TF * 4;
#pragma unroll
        for (int i = 0; i < 2; i++) {
            const int idx = tid + i * 256;
            const int r = idx >> 2, c4 = (idx & 3) * 4;
            const size_t go = (size_t)(m0 + r) * XW + kw0 + c4;
            const uint32_t so = (uint32_t)(r * IST + c4) * 4;
            cp_async16(a1 + so, Xq1 + go);
            cp_async16(a0 + so, Xq0 + go);
        }
#pragma unroll
        for (int i = 0; i < 2; i++) {
            const int idx = tid + i * 256;
            const int r = idx >> 2, c4 = (idx & 3) * 4;
            const size_t go = (size_t)(n0 + r) * XW + kw0 + c4;
            const uint32_t so = (uint32_t)(r * IST + c4) * 4;
            cp_async16(b1 + so, Wq1 + go);
            cp_async16(b0 + so, Wq0 + go);
        }
        cp_commit();
    };

    auto compute_stage = [&](int b) {
        const uint32_t* A1 = smu + b * I_BUFW;
        const uint32_t* A0 = A1 + I_TF;
        const uint32_t* B1 = A0 + I_TF;
        const uint32_t* B0 = B1 + I_TF;
#pragma unroll
        for (int k32 = 0; k32 < 2; k32++) {
            const int kb = k32 * 8;
            uint32_t a1[4][4], a0[4][4], b1[4][2], b0[4][2];
#pragma unroll
            for (int mt = 0; mt < 4; mt++) {
                const int ro = (wm0 + mt * 16 + g) * IST + kb;
                a1[mt][0] = A1[ro + t];
                a1[mt][1] = A1[ro + 8 * IST + t];
                a1[mt][2] = A1[ro + t + 4];
                a1[mt][3] = A1[ro + 8 * IST + t + 4];
                a0[mt][0] = A0[ro + t];
                a0[mt][1] = A0[ro + 8 * IST + t];
                a0[mt][2] = A0[ro + t + 4];
                a0[mt][3] = A0[ro + 8 * IST + t + 4];
            }
#pragma unroll
            for (int nt = 0; nt < 4; nt++) {
                const int no = (wn0 + nt * 8 + g) * IST + kb;
                b1[nt][0] = B1[no + t]; b1[nt][1] = B1[no + t + 4];
                b0[nt][0] = B0[no + t]; b0[nt][1] = B0[no + t + 4];
            }
#pragma unroll
            for (int mt = 0; mt < 4; mt++)
#pragma unroll
                for (int nt = 0; nt < 4; nt++)
                    MMA_S8(acc_hi[mt][nt], a1[mt], b1[nt]);
#pragma unroll
            for (int mt = 0; mt < 4; mt++)
#pragma unroll
                for (int nt = 0; nt < 4; nt++)
                    MMA_S8(acc_mid[mt][nt], a1[mt], b0[nt]);
#pragma unroll
            for (int mt = 0; mt < 4; mt++)
#pragma unroll
                for (int nt = 0; nt < 4; nt++)
                    MMA_S8(acc_mid[mt][nt], a0[mt], b1[nt]);
        }
    };

    load_stage(0, 0);
    constexpr int NS = D_ / 64;
    for (int s = 0; s < NS; s++) {
        const int b = s & 1;
        if (s + 1 < NS) {
            load_stage(s + 1, b ^ 1);
            cp_wait<1>();
        } else {
            cp_wait<0>();
        }
        __syncthreads();
        compute_stage(b);
        __syncthreads();
    }

#pragma unroll
    for (int mt = 0; mt < 4; mt++) {
#pragma unroll
        for (int half = 0; half < 2; half++) {
            const int m = m0 + wm0 + mt * 16 + g + half * 8;
            const int bb = m >> 11, l = m & (L_ - 1);
            const float sx = sxa[m];
#pragma unroll
            for (int nt = 0; nt < 4; nt++) {
                const int n = n0 + wn0 + nt * 8 + t * 2;
                const int e = half * 2;
                float2 v;
                v.x = ((float)acc_hi[mt][nt][e] * 4096.f
                     + (float)acc_mid[mt][nt][e] * 64.f) * (sx * swq[n]) + bias[n];
                v.y = ((float)acc_hi[mt][nt][e + 1] * 4096.f
                     + (float)acc_mid[mt][nt][e + 1] * 64.f) * (sx * swq[n + 1]) + bias[n + 1];

                const int sidx = n0 >> 10;
                const int h = (n >> 6) & (H_ - 1), dd = n & (HD_ - 1);
                const size_t row = (size_t)(bb * H_ + h) * L_ + l;
                const size_t woff = row * 32 + (dd >> 1);
                if (sidx == 0) {
                    uint32_t hw, lw;
                    bf16x2_split(v.x, v.y, hw, lw);
                    qh[woff] = hw; ql[woff] = lw;
                } else if (sidx == 1) {
                    uint32_t hw, lw;
                    bf16x2_split(v.x, v.y, hw, lw);
                    kh[woff] = hw; kl[woff] = lw;
                    *reinterpret_cast<float2*>(kraw + row * HD_ + dd) = v;
                } else {
                    *reinterpret_cast<float2*>(vraw + row * HD_ + dd) = v;
                    const float vxn = __shfl_down_sync(0xffffffffu, v.x, 4);
                    const float vyn = __shfl_down_sync(0xffffffffu, v.y, 4);
                    if ((g & 1) == 0) {
                        const size_t vb = (size_t)(bb * H_ + h) * HD_ * (L_ / 2);
                        const size_t l2 = (size_t)(l >> 1);
                        uint32_t hw, lw;
                        bf16x2_split(v.x, vxn, hw, lw);
                        vth[vb + (size_t)dd * (L_ / 2) + l2] = hw;
                        vtl[vb + (size_t)dd * (L_ / 2) + l2] = lw;
                        bf16x2_split(v.y, vyn, hw, lw);
                        vth[vb + (size_t)(dd + 1) * (L_ / 2) + l2] = hw;
                        vtl[vb + (size_t)(dd + 1) * (L_ / 2) + l2] = lw;
                    }
                }
            }
        }
    }
}

// ===========================================================================
// bf16x3 out-proj GEMM (R13, validated)
// ===========================================================================
#define GST 20
#define G_TF (128 * GST)
#define G_BUFW (4 * G_TF)
#define GEMM_SMEM (2 * G_BUFW * 4)

__global__ __launch_bounds__(256, 2)
void gemm_out(const uint32_t* __restrict__ Ahi, const uint32_t* __restrict__ Alo,
              const uint32_t* __restrict__ Whi, const uint32_t* __restrict__ Wlo,
              const float* __restrict__ bias, float* __restrict__ outF)
{
    extern __shared__ uint32_t smu[];
    const uint32_t sb = smem_u32(smu);

    const int tid  = threadIdx.x;
    const int lane = tid & 31;
    const int wid  = tid >> 5;
    const int g = lane >> 2;
    const int t = lane & 3;
    const int wm0 = (wid >> 2) * 64;
    const int wn0 = (wid & 3) * 32;
    const int m0 = blockIdx.y * 128;
    const int n0 = blockIdx.x * 128;

    const uint32_t laneA = (uint32_t)(((lane & 15) * GST + (lane >> 4) * 4) * 4);
    const uint32_t laneB = (uint32_t)((((lane & 7) + (lane >> 4) * 8) * GST
                                      + ((lane >> 3) & 1) * 4) * 4);

    float acc[4][4][4];
#pragma unroll
    for (int mt = 0; mt < 4; mt++)
#pragma unroll
        for (int nt = 0; nt < 4; nt++)
#pragma unroll
            for (int r = 0; r < 4; r++) acc[mt][nt][r] = 0.f;

    auto load_stage = [&](int s, int b) {
        const int kw0 = s * 16;
        const uint32_t aH = sb + (uint32_t)(b * G_BUFW) * 4;
        const uint32_t aL = aH + G_TF * 4;
        const uint32_t bH = aL + G_TF * 4;
        const uint32_t bL = bH + G_TF * 4;
#pragma unroll
        for (int i = 0; i < 2; i++) {
            const int idx = tid + i * 256;
            const int r = idx >> 2, c4 = (idx & 3) * 4;
            const size_t go = (size_t)(m0 + r) * PKW + kw0 + c4;
            const uint32_t so = (uint32_t)(r * GST + c4) * 4;
            cp_async16(aH + so, Ahi + go);
            cp_async16(aL + so, Alo + go);
        }
#pragma unroll
        for (int i = 0; i < 2; i++) {
            const int idx = tid + i * 256;
            const int r = idx >> 2, c4 = (idx & 3) * 4;
            const size_t go = (size_t)(n0 + r) * PKW + kw0 + c4;
            const uint32_t so = (uint32_t)(r * GST + c4) * 4;
            cp_async16(bH + so, Whi + go);
            cp_async16(bL + so, Wlo + go);
        }
        cp_commit();
    };

    auto compute_stage = [&](int b) {
        const uint32_t aH = sb + (uint32_t)(b * G_BUFW) * 4;
        const uint32_t aL = aH + G_TF * 4;
        const uint32_t bHa = aL + G_TF * 4;
        const uint32_t bLa = bHa + G_TF * 4;
#pragma unroll
        for (int k16 = 0; k16 < 2; k16++) {
            const uint32_t kboff = (uint32_t)(k16 * 32);
            uint32_t ah[4][4], al[4][4], bh[4][2], bl[4][2];
#pragma unroll
            for (int mt = 0; mt < 4; mt++) {
                const uint32_t base = (uint32_t)((wm0 + mt * 16) * GST * 4) + kboff + laneA;
                LDSM_X4(ah[mt][0], ah[mt][1], ah[mt][2], ah[mt][3], aH + base);
                LDSM_X4(al[mt][0], al[mt][1], al[mt][2], al[mt][3], aL + base);
            }
#pragma unroll
            for (int nt2 = 0; nt2 < 2; nt2++) {
                const uint32_t base = (uint32_t)((wn0 + nt2 * 16) * GST * 4) + kboff + laneB;
                LDSM_X4(bh[2 * nt2][0], bh[2 * nt2][1],
                        bh[2 * nt2 + 1][0], bh[2 * nt2 + 1][1], bHa + base);
                LDSM_X4(bl[2 * nt2][0], bl[2 * nt2][1],
                        bl[2 * nt2 + 1][0], bl[2 * nt2 + 1][1], bLa + base);
            }
#pragma unroll
            for (int mt = 0; mt < 4; mt++)
#pragma unroll
                for (int nt = 0; nt < 4; nt++)
                    MMA_BF16(acc[mt][nt], al[mt], bh[nt]);
#pragma unroll
            for (int mt = 0; mt < 4; mt++)
#pragma unroll
                for (int nt = 0; nt < 4; nt++)
                    MMA_BF16(acc[mt][nt], ah[mt], bl[nt]);
#pragma unroll
            for (int mt = 0; mt < 4; mt++)
#pragma unroll
                for (int nt = 0; nt < 4; nt++)
                    MMA_BF16(acc[mt][nt], ah[mt], bh[nt]);
        }
    };

    load_stage(0, 0);
    constexpr int NS = D_ / 32;
    for (int s = 0; s < NS; s++) {
        const int b = s & 1;
        if (s + 1 < NS) {
            load_stage(s + 1, b ^ 1);
            cp_wait<1>();
        } else {
            cp_wait<0>();
        }
        __syncthreads();
        compute_stage(b);
        __syncthreads();
    }

#pragma unroll
    for (int mt = 0; mt < 4; mt++) {
#pragma unroll
        for (int half = 0; half < 2; half++) {
            const int m = m0 + wm0 + mt * 16 + g + half * 8;
#pragma unroll
            for (int nt = 0; nt < 4; nt++) {
                const int n = n0 + wn0 + nt * 8 + t * 2;
                float2 v;
                v.x = acc[mt][nt][half * 2 + 0] + bias[n];
                v.y = acc[mt][nt][half * 2 + 1] + bias[n + 1];
                *reinterpret_cast<float2*>(outF + (size_t)m * D_ + n) = v;
            }
        }
    }
}

// ===========================================================================
// Flash attention (causal), bf16x3, exp/pack interleaved with PV MMA chunks.
// ===========================================================================
#define ATST 36
#define AQ_WORDS (128 * ATST)
#define ABUF0 (2 * AQ_WORDS)
#define AKV_TILE (64 * ATST)
#define ABUFW (4 * AKV_TILE)
#define ATTN_WORDS (ABUF0 + 2 * ABUFW)
#define ATTN_SMEM (ATTN_WORDS * 4)

__global__ __launch_bounds__(256, 2)
void attn_bf16(const uint32_t* __restrict__ qh_g, const uint32_t* __restrict__ ql_g,
               const uint32_t* __restrict__ kh_g, const uint32_t* __restrict__ kl_g,
               const uint32_t* __restrict__ vth_g, const uint32_t* __restrict__ vtl_g,
               uint32_t* __restrict__ ah_g, uint32_t* __restrict__ al_g)
{
    extern __shared__ uint32_t smu[];
    const uint32_t sb = smem_u32(smu);

    const int tidx = (int)gridDim.x - 1 - (int)blockIdx.x;
    const int bh   = blockIdx.y;
    const int row0 = tidx * 128;
    const uint32_t* qhp = qh_g + (size_t)bh * L_ * 32;
    const uint32_t* qlp = ql_g + (size_t)bh * L_ * 32;
    const uint32_t* khp = kh_g + (size_t)bh * L_ * 32;
    const uint32_t* klp = kl_g + (size_t)bh * L_ * 32;
    const uint32_t* vhp = vth_g + (size_t)bh * HD_ * (L_ / 2);
    const uint32_t* vlp = vtl_g + (size_t)bh * HD_ * (L_ / 2);

    const int tid = threadIdx.x;
    const int wid = tid >> 5;
    const int lane = tid & 31;
    const int g = lane >> 2;
    const int t = lane & 3;
    const int wrow = wid * 16;

    const uint32_t laneA = (uint32_t)(((lane & 15) * ATST + (lane >> 4) * 4) * 4);
    const uint32_t laneB = (uint32_t)((((lane & 7) + (lane >> 4) * 8) * ATST
                                      + ((lane >> 3) & 1) * 4) * 4);

    auto load_kv = [&](int c0, int b) {
        const uint32_t kH = sb + (uint32_t)(ABUF0 + b * ABUFW) * 4;
        const uint32_t kL = kH + AKV_TILE * 4;
        const uint32_t vH = kL + AKV_TILE * 4;
        const uint32_t vL = vH + AKV_TILE * 4;
#pragma unroll
        for (int i = 0; i < 2; i++) {
            const int idx = tid + i * 256;
            const int r = idx >> 3, c4 = (idx & 7) * 4;
            const uint32_t so = (uint32_t)(r * ATST + c4) * 4;
            cp_async16(kH + so, khp + (size_t)(c0 + r) * 32 + c4);
            cp_async16(kL + so, klp + (size_t)(c0 + r) * 32 + c4);
        }
#pragma unroll
        for (int i = 0; i < 2; i++) {
            const int idx = tid + i * 256;
            const int r = idx >> 3, c4 = (idx & 7) * 4;
            const uint32_t so = (uint32_t)(r * ATST + c4) * 4;
            cp_async16(vH + so, vhp + (size_t)r * (L_ / 2) + c0 / 2 + c4);
            cp_async16(vL + so, vlp + (size_t)r * (L_ / 2) + c0 / 2 + c4);
        }
        cp_commit();
    };
    load_kv(0, 0);

    uint32_t* Qh = smu;
    uint32_t* Ql = smu + AQ_WORDS;
#pragma unroll
    for (int i = 0; i < 2; i++) {
        const int idx = tid + i * 256;
        const int r = idx >> 2, c4 = (idx & 3) * 8;
        *reinterpret_cast<uint4*>(&Qh[r * ATST + c4]) =
            *reinterpret_cast<const uint4*>(qhp + (size_t)(row0 + r) * 32 + c4);
        *reinterpret_cast<uint4*>(&Qh[r * ATST + c4 + 4]) =
            *reinterpret_cast<const uint4*>(qhp + (size_t)(row0 + r) * 32 + c4 + 4);
        *reinterpret_cast<uint4*>(&Ql[r * ATST + c4]) =
            *reinterpret_cast<const uint4*>(qlp + (size_t)(row0 + r) * 32 + c4);
        *reinterpret_cast<uint4*>(&Ql[r * ATST + c4 + 4]) =
            *reinterpret_cast<const uint4*>(qlp + (size_t)(row0 + r) * 32 + c4 + 4);
    }
    const uint32_t QhA = sb;
    const uint32_t QlA = sb + AQ_WORDS * 4;

    float accO[8][4];
    float m_i[2] = { -1e30f, -1e30f };
    float l_i[2] = { 0.f, 0.f };
#pragma unroll
    for (int nt = 0; nt < 8; nt++)
#pragma unroll
        for (int e = 0; e < 4; e++) accO[nt][e] = 0.f;

    const int jmax = 2 * tidx + 1;
    for (int j0 = 0; j0 <= jmax; j0++) {
        const int c0 = j0 * 64;
        const int b = j0 & 1;

        cp_wait<0>();
        __syncthreads();

        if (j0 < jmax) load_kv(c0 + 64, b ^ 1);

        const uint32_t KH = sb + (uint32_t)(ABUF0 + b * ABUFW) * 4;
        const uint32_t KL = KH + AKV_TILE * 4;
        const uint32_t VH = KL + AKV_TILE * 4;
        const uint32_t VL = VH + AKV_TILE * 4;

        // ---- S = Q @ K^T ----
        float s[8][4];
#pragma unroll
        for (int nt = 0; nt < 8; nt++)
#pragma unroll
            for (int e = 0; e < 4; e++) s[nt][e] = 0.f;

#pragma unroll
        for (int k16 = 0; k16 < 4; k16++) {
            const uint32_t kboff = (uint32_t)(k16 * 32);
            uint32_t ah[4], al[4], bh2[8][2], bl2[8][2];
            const uint32_t qbase = (uint32_t)(wrow * ATST * 4) + kboff + laneA;
            LDSM_X4(ah[0], ah[1], ah[2], ah[3], QhA + qbase);
            LDSM_X4(al[0], al[1], al[2], al[3], QlA + qbase);
#pragma unroll
            for (int nt2 = 0; nt2 < 4; nt2++) {
                const uint32_t base = (uint32_t)(nt2 * 16 * ATST * 4) + kboff + laneB;
                LDSM_X4(bh2[2 * nt2][0], bh2[2 * nt2][1],
                        bh2[2 * nt2 + 1][0], bh2[2 * nt2 + 1][1], KH + base);
                LDSM_X4(bl2[2 * nt2][0], bl2[2 * nt2][1],
                        bl2[2 * nt2 + 1][0], bl2[2 * nt2 + 1][1], KL + base);
            }
#pragma unroll
            for (int nt = 0; nt < 8; nt++) MMA_BF16(s[nt], al, bh2[nt]);
#pragma unroll
            for (int nt = 0; nt < 8; nt++) MMA_BF16(s[nt], ah, bl2[nt]);
#pragma unroll
            for (int nt = 0; nt < 8; nt++) MMA_BF16(s[nt], ah, bh2[nt]);
        }

        // ---- scale + causal mask ----
        const bool dm = (c0 + 63 > row0);
        const int r0 = row0 + wrow + g;
        const int r1 = r0 + 8;
#pragma unroll
        for (int nt = 0; nt < 8; nt++) {
#pragma unroll
            for (int e = 0; e < 4; e++) {
                const int col = c0 + nt * 8 + 2 * t + (e & 1);
                const int row = (e < 2) ? r0 : r1;
                s[nt][e] *= SCALE_;
                if (dm && col > row) s[nt][e] = -1e30f;
            }
        }

        // ---- row max + correction (needs all of S) ----
        float mx0 = -1e30f, mx1 = -1e30f;
#pragma unroll
        for (int nt = 0; nt < 8; nt++) {
            mx0 = fmaxf(mx0, fmaxf(s[nt][0], s[nt][1]));
            mx1 = fmaxf(mx1, fmaxf(s[nt][2], s[nt][3]));
        }
#pragma unroll
        for (int off = 1; off <= 2; off <<= 1) {
            mx0 = fmaxf(mx0, __shfl_xor_sync(0xffffffffu, mx0, off));
            mx1 = fmaxf(mx1, __shfl_xor_sync(0xffffffffu, mx1, off));
        }
        const float mn0 = fmaxf(m_i[0], mx0);
        const float mn1 = fmaxf(m_i[1], mx1);
        const float corr0 = __expf(m_i[0] - mn0);
        const float corr1 = __expf(m_i[1] - mn1);
        m_i[0] = mn0; m_i[1] = mn1;
#pragma unroll
        for (int nt = 0; nt < 8; nt++) {
            accO[nt][0] *= corr0; accO[nt][1] *= corr0;
            accO[nt][2] *= corr1; accO[nt][3] *= corr1;
        }

        // ---- interleaved: exp+pack chunk ks, then its PV MMAs ----
        float ls0 = 0.f, ls1 = 0.f;
#pragma unroll
        for (int ks = 0; ks < 4; ks++) {
            uint32_t pah[4], pal[4];
#pragma unroll
            for (int j = 0; j < 2; j++) {
                const int nt = 2 * ks + j;
                s[nt][0] = __expf(s[nt][0] - mn0);
                s[nt][1] = __expf(s[nt][1] - mn0);
                s[nt][2] = __expf(s[nt][2] - mn1);
                s[nt][3] = __expf(s[nt][3] - mn1);
                ls0 += s[nt][0] + s[nt][1];
                ls1 += s[nt][2] + s[nt][3];
                bf16x2_split(s[nt][0], s[nt][1], pah[2 * j], pal[2 * j]);
                bf16x2_split(s[nt][2], s[nt][3], pah[2 * j + 1], pal[2 * j + 1]);
            }
            const uint32_t kboff = (uint32_t)(ks * 32);
            uint32_t vh[8][2], vl[8][2];
#pragma unroll
            for (int nt2 = 0; nt2 < 4; nt2++) {
                const uint32_t base = (uint32_t)(nt2 * 16 * ATST * 4) + kboff + laneB;
                LDSM_X4(vh[2 * nt2][0], vh[2 * nt2][1],
                        vh[2 * nt2 + 1][0], vh[2 * nt2 + 1][1], VH + base);
                LDSM_X4(vl[2 * nt2][0], vl[2 * nt2][1],
                        vl[2 * nt2 + 1][0], vl[2 * nt2 + 1][1], VL + base);
            }
#pragma unroll
            for (int nt = 0; nt < 8; nt++) MMA_BF16(accO[nt], pal, vh[nt]);
#pragma unroll
            for (int nt = 0; nt < 8; nt++) MMA_BF16(accO[nt], pah, vl[nt]);
#pragma unroll
            for (int nt = 0; nt < 8; nt++) MMA_BF16(accO[nt], pah, vh[nt]);
        }

        // ---- finish l update ----
#pragma unroll
        for (int off = 1; off <= 2; off <<= 1) {
            ls0 += __shfl_xor_sync(0xffffffffu, ls0, off);
            ls1 += __shfl_xor_sync(0xffffffffu, ls1, off);
        }
        l_i[0] = l_i[0] * corr0 + ls0;
        l_i[1] = l_i[1] * corr1 + ls1;
    }

    const int bb = bh >> 4;
    const int h  = bh & (H_ - 1);
    const float inv0 = 1.0f / l_i[0];
    const float inv1 = 1.0f / l_i[1];
    const int r0 = row0 + wrow + g;
#pragma unroll
    for (int nt = 0; nt < 8; nt++) {
        const int widx = h * 32 + nt * 4 + t;
        uint32_t hw, lw;
        bf16x2_split(accO[nt][0] * inv0, accO[nt][1] * inv0, hw, lw);
        ah_g[((size_t)(bb * L_ + r0)) * 512 + widx] = hw;
        al_g[((size_t)(bb * L_ + r0)) * 512 + widx] = lw;
        bf16x2_split(accO[nt][2] * inv1, accO[nt][3] * inv1, hw, lw);
        ah_g[((size_t)(bb * L_ + r0 + 8)) * 512 + widx] = hw;
        al_g[((size_t)(bb * L_ + r0 + 8)) * 512 + widx] = lw;
    }
}

// ---------------------------------------------------------------------------
extern "C" void kernel_launch(void* const* d_in, const int* in_sizes, int n_in,
                              void* d_out, int out_size)
{
    const float* x     = (const float*)d_in[0];
    const float* w_qkv = (const float*)d_in[1];
    const float* b_qkv = (const float*)d_in[2];
    const float* w_out = (const float*)d_in[3];
    const float* b_out = (const float*)d_in[4];

    float* out  = (float*)d_out;
    float* kout = out  + (size_t)B_ * L_ * D_;
    float* vout = kout + NQKV;

    uint32_t *xq1, *xq0, *wq1, *wq0, *woh, *wol;
    uint32_t *qh, *ql, *kh, *kl, *vth, *vtl, *ah, *al;
    float *sxa, *swq;
    cudaGetSymbolAddress((void**)&xq1, g_xq1);
    cudaGetSymbolAddress((void**)&xq0, g_xq0);
    cudaGetSymbolAddress((void**)&wq1, g_wq1);
    cudaGetSymbolAddress((void**)&wq0, g_wq0);
    cudaGetSymbolAddress((void**)&sxa, g_sxa);
    cudaGetSymbolAddress((void**)&swq, g_swq);
    cudaGetSymbolAddress((void**)&woh, g_woh);
    cudaGetSymbolAddress((void**)&wol, g_wol);
    cudaGetSymbolAddress((void**)&qh, g_qh);
    cudaGetSymbolAddress((void**)&ql, g_ql);
    cudaGetSymbolAddress((void**)&kh, g_kh);
    cudaGetSymbolAddress((void**)&kl, g_kl);
    cudaGetSymbolAddress((void**)&vth, g_vth);
    cudaGetSymbolAddress((void**)&vtl, g_vtl);
    cudaGetSymbolAddress((void**)&ah, g_ah);
    cudaGetSymbolAddress((void**)&al, g_al);

    cudaFuncSetAttribute(gemm_i8_qkv,
                         cudaFuncAttributeMaxDynamicSharedMemorySize, IGEMM_SMEM);
    cudaFuncSetAttribute(gemm_out,
                         cudaFuncAttributeMaxDynamicSharedMemorySize, GEMM_SMEM);
    cudaFuncSetAttribute(attn_bf16,
                         cudaFuncAttributeMaxDynamicSharedMemorySize, ATTN_SMEM);

    // 0) Prep: 2 merged launches
    prep1<<<CMB + WOB, 256>>>(w_qkv, w_out, swq, woh, wol);
    prep2<<<XQB + WQB, 256>>>(x, w_qkv, swq, xq1, xq0, sxa, wq1, wq0);

    // 1) QKV projection (int8 limb IMMA)
    gemm_i8_qkv<<<dim3(24, 32), 256, IGEMM_SMEM>>>(
        xq1, xq0, wq1, wq0, sxa, swq, b_qkv,
        qh, ql, kh, kl, vth, vtl, kout, vout);

    // 2) Causal flash attention (bf16x3, interleaved softmax/PV)
    attn_bf16<<<dim3(L_ / 128, B_ * H_), 256, ATTN_SMEM>>>(
        qh, ql, kh, kl, vth, vtl, ah, al);

    // 3) Output projection (bf16x3)
    gemm_out<<<dim3(8, 32), 256, GEMM_SMEM>>>(ah, al, woh, wol, b_out, out);
}